// round 8
// baseline (speedup 1.0000x reference)
#include <cuda_runtime.h>

// Gaussian-splat render, round 5.
//   out[n,c] = sum_m exp(-0.5 * d^T C_m^-1 d) * cols[m,c]
//
// R4 (71.9us): fma 55.7%, latency-bound; regs 114 -> no more TLP possible.
// R5: more ILP at same occupancy.
//  * P=8 pairs/thread (8 independent chains/warp), Q=16 slices of 128 G.
//  * Horner form of the quadratic: depth-3 FMA chain, no xx/xy/yy regs
//    (-24 regs -> P=8 fits under the 128-reg/thread RF wall at BLK=512).
//  * Same lane-duplicated f32x2 table (5 LDS.128/G, amortized over 8 pairs).

typedef unsigned long long u64;

static constexpr int N_GAUSS = 2048;
static constexpr int N_PAIR  = 32768;        // 65536 pixels / 2
static constexpr int P       = 8;            // pairs per thread
static constexpr int Q       = 16;           // Gaussian slices
static constexpr int GQ      = N_GAUSS / Q;  // 128 per thread
static constexpr int NSLOT   = N_PAIR / P;   // 4096 pair-slots
static constexpr int SPB     = 32;           // slots per CTA (warp-aligned)
static constexpr int BLK     = SPB * Q;      // 512 threads
static constexpr int GRID    = 148;
static constexpr int SLOTS   = 10;           // u64 per Gaussian (5 x LDS.128)
static constexpr size_t SMEM_BYTES = (size_t)N_GAUSS * SLOTS * sizeof(u64); // 160KB

__device__ u64 g_tab[N_GAUSS * SLOTS];

__device__ __forceinline__ u64 pack2(float lo, float hi) {
    u64 r; asm("mov.b64 %0, {%1, %2};" : "=l"(r) : "f"(lo), "f"(hi)); return r;
}
__device__ __forceinline__ void unpack2(u64 v, float& lo, float& hi) {
    asm("mov.b64 {%0, %1}, %2;" : "=f"(lo), "=f"(hi) : "l"(v));
}
__device__ __forceinline__ u64 fma2(u64 a, u64 b, u64 c) {
    u64 d; asm("fma.rn.f32x2 %0, %1, %2, %3;" : "=l"(d) : "l"(a), "l"(b), "l"(c)); return d;
}
__device__ __forceinline__ float ex2f(float v) {
    float r; asm("ex2.approx.f32 %0, %1;" : "=f"(r) : "f"(v)); return r;
}

// ---- Prep: per-Gaussian coefficient + color table (lane-duplicated) ----
__global__ void prep_kernel(const float* __restrict__ mus,
                            const float* __restrict__ covs,
                            const float* __restrict__ cols)
{
    int m = blockIdx.x * blockDim.x + threadIdx.x;
    if (m >= N_GAUSS) return;

    const float s = -0.72134752044448170368f;  // -0.5 * log2(e)
    float2 mu = ((const float2*)mus)[m];
    float4 cv = ((const float4*)covs)[m];      // [a, b, b, c]
    float a = cv.x, b = cv.y, c = cv.w;
    float inv_det = 1.0f / (a * c - b * b);
    float p00 =  c * inv_det;
    float p01 = -b * inv_det;
    float p11 =  a * inv_det;

    float cxx = s * p00;
    float cxy = s * (2.0f * p01);
    float cyy = s * p11;
    float l1 = p00 * mu.x + p01 * mu.y;
    float l2 = p01 * mu.x + p11 * mu.y;
    float cx = s * (-2.0f * l1);
    float cy = s * (-2.0f * l2);
    float c0 = s * (mu.x * l1 + mu.y * l2);

    float r  = cols[3 * m + 0];
    float g  = cols[3 * m + 1];
    float bl = cols[3 * m + 2];

    u64* q = g_tab + (size_t)m * SLOTS;
    q[0] = pack2(cxx, cxx);
    q[1] = pack2(cxy, cxy);
    q[2] = pack2(cyy, cyy);
    q[3] = pack2(cx,  cx);
    q[4] = pack2(cy,  cy);
    q[5] = pack2(c0,  c0);
    q[6] = pack2(r,   r);
    q[7] = pack2(g,   g);
    q[8] = pack2(bl,  bl);
    q[9] = 0ull;
}

// ---- Main render ----
__global__ __launch_bounds__(BLK, 1)
void render_kernel(const float* __restrict__ x, float* __restrict__ out)
{
    extern __shared__ u64 sh[];
    const int tid = threadIdx.x;

    // bulk copy table into shared
    {
        const ulonglong2* src = (const ulonglong2*)g_tab;
        ulonglong2* dst = (ulonglong2*)sh;
        #pragma unroll 4
        for (int i = tid; i < N_GAUSS * SLOTS / 2; i += BLK) dst[i] = src[i];
    }
    __syncthreads();

    const int slice = tid >> 5;                   // 0..15, one warp per slice
    const int slot  = tid & (SPB - 1);            // 0..31
    const int sg    = blockIdx.x + GRID * slot;   // round-robin pair-slot
    const bool active = (sg < NSLOT);

    u64 X1[P], X2[P];
    u64 aR[P], aG[P], aB[P];

    if (active) {
        #pragma unroll
        for (int i = 0; i < P; ++i) {
            float4 xv = ((const float4*)x)[sg + NSLOT * i];
            X1[i] = pack2(xv.x, xv.z);
            X2[i] = pack2(xv.y, xv.w);
            aR[i] = 0ull; aG[i] = 0ull; aB[i] = 0ull;
        }

        const ulonglong2* S = (const ulonglong2*)sh;   // 5 x LDS.128 per Gaussian
        const int mbase = slice * GQ;

        #pragma unroll 2
        for (int j = 0; j < GQ; ++j) {
            const int m = mbase + j;
            ulonglong2 v0 = S[m * 5 + 0];  // {cxx} {cxy}
            ulonglong2 v1 = S[m * 5 + 1];  // {cyy} {cx }
            ulonglong2 v2 = S[m * 5 + 2];  // {cy } {c0 }
            ulonglong2 v3 = S[m * 5 + 3];  // {r  } {g  }
            ulonglong2 v4 = S[m * 5 + 4];  // {b  } {pad}

            #pragma unroll
            for (int i = 0; i < P; ++i) {
                // Horner: t = x*(cxx*x + cxy*y + cx) + (y*(cyy*y + cy) + c0)
                u64 u = fma2(v0.y, X2[i], v1.y);   // cxy*y + cx
                u     = fma2(v0.x, X1[i], u);      // + cxx*x
                u64 v = fma2(v1.x, X2[i], v2.x);   // cyy*y + cy
                u64 t = fma2(X2[i], v, v2.y);      // y*(..) + c0
                t     = fma2(X1[i], u, t);         // + x*(..)

                float tl, th;
                unpack2(t, tl, th);
                u64 w = pack2(ex2f(tl), ex2f(th));

                aR[i] = fma2(v3.x, w, aR[i]);
                aG[i] = fma2(v3.y, w, aG[i]);
                aB[i] = fma2(v4.x, w, aB[i]);
            }
        }
    }

    // ---- cross-slice reduction via shared (reuse coeff region) ----
    __syncthreads();                  // all reads of S done
    float* red = (float*)sh;          // [Q-1][SPB][P][6]
    if (slice != 0 && active) {
        float* qp = red + (((slice - 1) * SPB + slot) * P) * 6;
        #pragma unroll
        for (int i = 0; i < P; ++i) {
            float r0, r1, g0, g1, b0, b1;
            unpack2(aR[i], r0, r1);
            unpack2(aG[i], g0, g1);
            unpack2(aB[i], b0, b1);
            float* qq = qp + i * 6;
            qq[0] = r0; qq[1] = r1; qq[2] = g0; qq[3] = g1; qq[4] = b0; qq[5] = b1;
        }
    }
    __syncthreads();
    if (slice == 0 && active) {
        #pragma unroll
        for (int i = 0; i < P; ++i) {
            float r0, r1, g0, g1, b0, b1;
            unpack2(aR[i], r0, r1);
            unpack2(aG[i], g0, g1);
            unpack2(aB[i], b0, b1);
            for (int qd = 0; qd < Q - 1; ++qd) {
                const float* qq = red + (((qd * SPB + slot) * P) + i) * 6;
                r0 += qq[0]; r1 += qq[1];
                g0 += qq[2]; g1 += qq[3];
                b0 += qq[4]; b1 += qq[5];
            }
            const int p = sg + NSLOT * i;        // pair index
            float2* o = (float2*)(out + (size_t)p * 6);
            o[0] = make_float2(r0, g0);
            o[1] = make_float2(b0, r1);
            o[2] = make_float2(g1, b1);
        }
    }
}

extern "C" void kernel_launch(void* const* d_in, const int* in_sizes, int n_in,
                              void* d_out, int out_size)
{
    const float* x    = (const float*)d_in[0];
    const float* mus  = (const float*)d_in[1];
    const float* covs = (const float*)d_in[2];
    const float* cols = (const float*)d_in[3];
    float* out = (float*)d_out;

    prep_kernel<<<(N_GAUSS + 255) / 256, 256>>>(mus, covs, cols);

    cudaFuncSetAttribute(render_kernel,
                         cudaFuncAttributeMaxDynamicSharedMemorySize,
                         (int)SMEM_BYTES);
    render_kernel<<<GRID, BLK, SMEM_BYTES>>>(x, out);
}